// round 12
// baseline (speedup 1.0000x reference)
#include <cuda_runtime.h>
#include <math.h>

#define D_EMBED 2048
#define SEQ     2048
#define NH      32
#define HD      64
#define D3      (3 * D_EMBED)       // 6144

// Scratch (allocation-free rule)
__device__ float g_qkv[SEQ * D3];             // [2048,6144] qkv (tf32-rounded)
__device__ float g_attn[SEQ * D_EMBED];       // [2048,2048] attn out (tf32-rounded)
__device__ float g_hid_t[SEQ * D_EMBED];      // tf32-rounded hidden
__device__ float g_wqkv_t[D3 * D_EMBED];      // tf32-rounded w_qkv
__device__ float g_wout_t[D_EMBED * D_EMBED]; // tf32-rounded w_out

// ===========================================================================
// Helpers (base sm_100 portable: mma.sync / ldmatrix / cp.async only)
// ===========================================================================
__device__ __forceinline__ unsigned smem_u32(const void* p) {
    unsigned a;
    asm("{ .reg .u64 t; cvta.to.shared.u64 t, %1; cvt.u32.u64 %0, t; }"
        : "=r"(a) : "l"(p));
    return a;
}
#define CP_ASYNC16(dst, src) \
    asm volatile("cp.async.cg.shared.global [%0], [%1], 16;" :: "r"(dst), "l"(src))
#define CP_COMMIT() asm volatile("cp.async.commit_group;" ::: "memory")
#define CP_WAIT(n)  asm volatile("cp.async.wait_group %0;" :: "n"(n) : "memory")

__device__ __forceinline__ void ldsm_x4(unsigned r[4], unsigned addr) {
    asm volatile("ldmatrix.sync.aligned.m8n8.x4.shared.b16 {%0,%1,%2,%3}, [%4];"
                 : "=r"(r[0]), "=r"(r[1]), "=r"(r[2]), "=r"(r[3]) : "r"(addr));
}
__device__ __forceinline__ void mma_tf32(float c[4], const unsigned a[4],
                                         unsigned b0, unsigned b1) {
    asm volatile("mma.sync.aligned.m16n8k8.row.col.f32.tf32.tf32.f32 "
                 "{%0,%1,%2,%3}, {%4,%5,%6,%7}, {%8,%9}, {%0,%1,%2,%3};"
                 : "+f"(c[0]), "+f"(c[1]), "+f"(c[2]), "+f"(c[3])
                 : "r"(a[0]), "r"(a[1]), "r"(a[2]), "r"(a[3]), "r"(b0), "r"(b1));
}
__device__ __forceinline__ float round_tf32(float x) {
    unsigned u;
    asm("cvt.rna.tf32.f32 %0, %1;" : "=r"(u) : "f"(x));
    return __uint_as_float(u);
}
__device__ __forceinline__ float fast_exp2(float x) {
    float y;
    asm("ex2.approx.f32 %0, %1;" : "=f"(y) : "f"(x));
    return y;
}

// ===========================================================================
// Fused RN-round-to-tf32 over the three GEMM-input buffers (1 launch)
// ===========================================================================
#define N4_HID  (SEQ * D_EMBED / 4)
#define N4_WQKV (D3 * D_EMBED / 4)
#define N4_WOUT (D_EMBED * D_EMBED / 4)
#define N4_ALL  (N4_HID + N4_WQKV + N4_WOUT)

__global__ void round_all_kernel(const float4* __restrict__ hid,
                                 const float4* __restrict__ wqkv,
                                 const float4* __restrict__ wout,
                                 float4* __restrict__ hid_t,
                                 float4* __restrict__ wqkv_t,
                                 float4* __restrict__ wout_t)
{
    int i = blockIdx.x * blockDim.x + threadIdx.x;
    if (i >= N4_ALL) return;
    const float4* src;
    float4* dst;
    int j;
    if (i < N4_HID)                { src = hid;  dst = hid_t;  j = i; }
    else if (i < N4_HID + N4_WQKV) { src = wqkv; dst = wqkv_t; j = i - N4_HID; }
    else                           { src = wout; dst = wout_t; j = i - N4_HID - N4_WQKV; }
    float4 v = src[j];
    v.x = round_tf32(v.x); v.y = round_tf32(v.y);
    v.z = round_tf32(v.z); v.w = round_tf32(v.w);
    dst[j] = v;
}

// ===========================================================================
// tf32 mma.sync NT GEMM + bias, PERSISTENT grid (R8-proven, untouched).
// ===========================================================================
#define BM 128
#define BN 128
#define BK 32
#define STAGES 3
#define AS_BYTES (BM * 128)
#define BS_BYTES (BN * 128)
#define STG_BYTES (AS_BYTES + BS_BYTES)
#define GEMM_SMEM_BYTES (STAGES * STG_BYTES)  // 96 KB
#define GEMM_GRID 296                          // 148 SMs x 2 resident CTAs

__global__ __launch_bounds__(256, 2)
void gemm_tf32mma(const float* __restrict__ A, const float* __restrict__ B,
                  const float* __restrict__ bias, float* __restrict__ C,
                  int N, int K, int M, int round_c)
{
    extern __shared__ char smem[];
    const unsigned sb = smem_u32(smem);
    const int tid  = threadIdx.x;
    const int wid  = tid >> 5;
    const int lane = tid & 31;
    const int m_off = (wid & 1) * 64;
    const int n_off = (wid >> 1) * 32;
    const int NC = K / BK;
    const int ntx = N / BN;
    const int ntiles = ntx * (M / BM);

    const int rA  = lane & 15;
    const unsigned hiA = ((lane >> 4) & 1) * 16;
    const int rB  = (lane & 7) + ((lane >> 4) & 1) * 8;
    const unsigned hiB = ((lane >> 3) & 1) * 16;
    const int g = lane >> 2;
    const int cc = (lane & 3) * 2;

    for (int t = blockIdx.x; t < ntiles; t += gridDim.x) {
        const int m0 = (t / ntx) * BM;
        const int n0 = (t % ntx) * BN;

        __syncthreads();            // all warps done reading smem of prev tile

        float acc[4][4][4];
#pragma unroll
        for (int mi = 0; mi < 4; mi++)
#pragma unroll
            for (int nf = 0; nf < 4; nf++)
#pragma unroll
                for (int j = 0; j < 4; j++) acc[mi][nf][j] = 0.f;

        auto load_chunk = [&](int ck, int st) {
            const unsigned ab = sb + st * STG_BYTES;
            const unsigned bb = ab + AS_BYTES;
            const float* Ag = A + (size_t)m0 * K + ck * BK;
            const float* Bg = B + (size_t)n0 * K + ck * BK;
#pragma unroll
            for (int i = 0; i < 4; i++) {
                int seg = tid + i * 256;
                int r = seg >> 3, s16 = seg & 7;
                unsigned col = (unsigned)(s16 * 16) ^ ((unsigned)(r & 7) * 16);
                CP_ASYNC16(ab + r * 128 + col, Ag + (size_t)r * K + s16 * 4);
                CP_ASYNC16(bb + r * 128 + col, Bg + (size_t)r * K + s16 * 4);
            }
            CP_COMMIT();
        };

        for (int p = 0; p < STAGES - 1; p++) load_chunk(p, p);

        for (int c = 0; c < NC; c++) {
            CP_WAIT(STAGES - 2);
            __syncthreads();
            if (c + STAGES - 1 < NC) load_chunk(c + STAGES - 1, (c + STAGES - 1) % STAGES);
            else                     CP_COMMIT();

            const unsigned ab = sb + (c % STAGES) * STG_BYTES;
            const unsigned bb = ab + AS_BYTES;
#pragma unroll
            for (int ks = 0; ks < 4; ks++) {
                unsigned a[4][4], b[2][4];
#pragma unroll
                for (int mi = 0; mi < 4; mi++) {
                    int row = m_off + mi * 16 + rA;
                    unsigned col = ((unsigned)(ks * 32) + hiA) ^ ((unsigned)(row & 7) * 16);
                    ldsm_x4(a[mi], ab + row * 128 + col);
                }
#pragma unroll
                for (int nj = 0; nj < 2; nj++) {
                    int row = n_off + nj * 16 + rB;
                    unsigned col = ((unsigned)(ks * 32) + hiB) ^ ((unsigned)(row & 7) * 16);
                    ldsm_x4(b[nj], bb + row * 128 + col);
                }
#pragma unroll
                for (int mi = 0; mi < 4; mi++)
#pragma unroll
                    for (int nf = 0; nf < 4; nf++)
                        mma_tf32(acc[mi][nf], a[mi],
                                 b[nf >> 1][(nf & 1) * 2], b[nf >> 1][(nf & 1) * 2 + 1]);
            }
        }

#pragma unroll
        for (int nf = 0; nf < 4; nf++) {
            int col = n0 + n_off + nf * 8 + cc;
            float b0 = bias[col], b1 = bias[col + 1];
#pragma unroll
            for (int mi = 0; mi < 4; mi++) {
                int r = m0 + m_off + mi * 16 + g;
                float2 v0 = make_float2(acc[mi][nf][0] + b0, acc[mi][nf][1] + b1);
                float2 v1 = make_float2(acc[mi][nf][2] + b0, acc[mi][nf][3] + b1);
                if (round_c) {
                    v0.x = round_tf32(v0.x); v0.y = round_tf32(v0.y);
                    v1.x = round_tf32(v1.x); v1.y = round_tf32(v1.y);
                }
                *(float2*)(C + (size_t)r * N + col)       = v0;
                *(float2*)(C + (size_t)(r + 8) * N + col) = v1;
            }
        }
    }
}

// ===========================================================================
// tf32 mma.sync causal flash attention. R8 base + this round:
//  - Q A-frags cached in registers (loaded once at kt==0): -8 LDSM per kt
//  - next-K prefetch hoisted to top of iteration (full-iter latency hiding)
// ===========================================================================
#define FA_Q 0
#define FA_K 16384                  // 2 stages x 16 KB
#define FA_V 49152                  // 64 x 272 B = 17408
#define FA_P 66560                  // 4 warps x 4 KB
#define FA_SMEM 82944
#define CST 0.1803368801111137f     // (1/8) * log2(e)

__global__ __launch_bounds__(128)
void flash_attn_mma(const float* __restrict__ qkv, float* __restrict__ attn)
{
    extern __shared__ char smc[];
    const unsigned sb = smem_u32(smc);
    const int tid = threadIdx.x;
    const int wid = tid >> 5, lane = tid & 31;
    const int qb = gridDim.x - 1 - blockIdx.x;     // LPT: big CTAs first
    const int h  = blockIdx.y;
    const int qbase = qb * 64;
    const int g = lane >> 2, qq = lane & 3;

    const int rA = lane & 15;
    const unsigned hiA = ((lane >> 4) & 1) * 16;
    const int rB = (lane & 7) + ((lane >> 4) & 1) * 8;
    const unsigned hiB = ((lane >> 3) & 1) * 16;

    // 64x64 f32 tile copy: 256B rows, XOR-16B swizzle per 128B half
    auto tile_async = [&](const float* gsrc, unsigned dstb) {
#pragma unroll
        for (int i = 0; i < 8; i++) {
            int u = tid + i * 128;
            int r = u >> 4, hs = (u >> 3) & 1, s16 = u & 7;
            unsigned off = ((unsigned)(s16 * 16)) ^ ((unsigned)(r & 7) * 16);
            CP_ASYNC16(dstb + (unsigned)(r * 256 + hs * 128) + off,
                       gsrc + (size_t)r * D3 + hs * 32 + s16 * 4);
        }
    };

    const float* Qg = qkv + (size_t)qbase * D3 + h * HD;
    const float* Kg = qkv + D_EMBED + h * HD;
    const float* Vg = qkv + 2 * D_EMBED + h * HD;

    tile_async(Qg, sb + FA_Q);
    tile_async(Kg, sb + FA_K);      // K tile 0 -> stage 0
    CP_COMMIT();

    float o[8][4];
#pragma unroll
    for (int nf = 0; nf < 8; nf++)
#pragma unroll
        for (int j = 0; j < 4; j++) o[nf][j] = 0.f;
    float m0 = -1e30f, m1 = -1e30f, l0 = 0.f, l1 = 0.f;

    unsigned aq[8][4];              // Q A-frags, cached at kt==0
    const int vd = tid & 63, vkh = tid >> 6;       // V gather mapping

    for (int kt = 0; kt <= qb; kt++) {
        const int st = kt & 1;
        CP_WAIT(0);                 // K[kt] (and Q on first iter) resident
        __syncthreads();            // all warps done with prev tile (VsT reuse safe)

        // ---- next-K prefetch FIRST: stage st^1 is free; hide under whole iter
        if (kt < qb)
            tile_async(Kg + (size_t)(kt + 1) * 64 * D3, sb + FA_K + (st ^ 1) * 16384);
        CP_COMMIT();

        // ---- V gather LDGs -> registers (overlap with S MMA below)
        float4 vr[8];
        {
            const float* src = Vg + (size_t)kt * 64 * D3 + vd;
#pragma unroll
            for (int j = 0; j < 8; j++) {
                int k0 = vkh * 32 + j * 4;
                vr[j].x = src[(size_t)(k0 + 0) * D3];
                vr[j].y = src[(size_t)(k0 + 1) * D3];
                vr[j].z = src[(size_t)(k0 + 2) * D3];
                vr[j].w = src[(size_t)(k0 + 3) * D3];
            }
        }

        // ---- cache Q A-frags once (Q tile never changes)
        if (kt == 0) {
#pragma unroll
            for (int ks = 0; ks < 8; ks++) {
                int row = wid * 16 + rA;
                unsigned addr = sb + FA_Q + (unsigned)(row * 256 + (ks >> 2) * 128)
                              + (((unsigned)((ks & 3) * 32) + hiA) ^ ((unsigned)(row & 7) * 16));
                ldsm_x4(aq[ks], addr);
            }
        }

        // ---- S = Q K^T  (16 q-rows x 64 keys per warp)
        const unsigned kb = sb + FA_K + st * 16384;
        float sf[8][4];
#pragma unroll
        for (int nf = 0; nf < 8; nf++)
#pragma unroll
            for (int j = 0; j < 4; j++) sf[nf][j] = 0.f;
#pragma unroll
        for (int ks = 0; ks < 8; ks++) {
            unsigned b[4][4];
#pragma unroll
            for (int nj = 0; nj < 4; nj++) {
                int row = nj * 16 + rB;
                unsigned addr = kb + (unsigned)(row * 256 + (ks >> 2) * 128)
                              + (((unsigned)((ks & 3) * 32) + hiB) ^ ((unsigned)(row & 7) * 16));
                ldsm_x4(b[nj], addr);
            }
#pragma unroll
            for (int nf = 0; nf < 8; nf++)
                mma_tf32(sf[nf], aq[ks], b[nf >> 1][(nf & 1) * 2], b[nf >> 1][(nf & 1) * 2 + 1]);
        }

        // ---- V STS (loads landed during S MMA): VsT[d][key], row stride 272B
#pragma unroll
        for (int j = 0; j < 8; j++) {
            int k0 = vkh * 32 + j * 4;
            *(float4*)(smc + FA_V + vd * 272 + k0 * 4) = vr[j];
        }

        // ---- online softmax on fragments (log2 domain)
        if (kt == qb) {
            int r0 = qbase + wid * 16 + g;
#pragma unroll
            for (int nf = 0; nf < 8; nf++) {
                int col = qbase + nf * 8 + qq * 2;
                if (col > r0)         sf[nf][0] = -1e30f;
                if (col + 1 > r0)     sf[nf][1] = -1e30f;
                if (col > r0 + 8)     sf[nf][2] = -1e30f;
                if (col + 1 > r0 + 8) sf[nf][3] = -1e30f;
            }
        }
        float t0 = -1e30f, t1 = -1e30f;
#pragma unroll
        for (int nf = 0; nf < 8; nf++) {
            t0 = fmaxf(t0, fmaxf(sf[nf][0], sf[nf][1]));
            t1 = fmaxf(t1, fmaxf(sf[nf][2], sf[nf][3]));
        }
        t0 = fmaxf(t0, __shfl_xor_sync(0xffffffffu, t0, 1));
        t0 = fmaxf(t0, __shfl_xor_sync(0xffffffffu, t0, 2));
        t1 = fmaxf(t1, __shfl_xor_sync(0xffffffffu, t1, 1));
        t1 = fmaxf(t1, __shfl_xor_sync(0xffffffffu, t1, 2));
        const float mn0 = fmaxf(m0, t0 * CST);
        const float mn1 = fmaxf(m1, t1 * CST);
        const float al0 = fast_exp2(m0 - mn0);
        const float al1 = fast_exp2(m1 - mn1);
        m0 = mn0; m1 = mn1;

        float ps0 = 0.f, ps1 = 0.f;
        const int pwo = FA_P + wid * 4096;
#pragma unroll
        for (int nf = 0; nf < 8; nf++) {
            float p00 = round_tf32(fast_exp2(fmaf(sf[nf][0], CST, -mn0)));
            float p01 = round_tf32(fast_exp2(fmaf(sf[nf][1], CST, -mn0)));
            float p10 = round_tf32(fast_exp2(fmaf(sf[nf][2], CST, -mn1)));
            float p11 = round_tf32(fast_exp2(fmaf(sf[nf][3], CST, -mn1)));
            ps0 += p00 + p01; ps1 += p10 + p11;
            unsigned offh = ((unsigned)((nf & 3) * 32 + qq * 8)) ^ ((unsigned)g * 16);
            int base = pwo + (nf >> 2) * 128 + (int)offh;
            *(float2*)(smc + base + g * 256)       = make_float2(p00, p01);
            *(float2*)(smc + base + (g + 8) * 256) = make_float2(p10, p11);
        }
        ps0 += __shfl_xor_sync(0xffffffffu, ps0, 1);
        ps0 += __shfl_xor_sync(0xffffffffu, ps0, 2);
        ps1 += __shfl_xor_sync(0xffffffffu, ps1, 1);
        ps1 += __shfl_xor_sync(0xffffffffu, ps1, 2);
        l0 = l0 * al0 + ps0;
        l1 = l1 * al1 + ps1;
#pragma unroll
        for (int nf = 0; nf < 8; nf++) {
            o[nf][0] *= al0; o[nf][1] *= al0;
            o[nf][2] *= al1; o[nf][3] *= al1;
        }
        __syncwarp();               // P visible within warp
        __syncthreads();            // VsT + P visible to all warps

        // ---- O += P * V  (P A-frags from smem, V^T B-frags)
#pragma unroll
        for (int ks = 0; ks < 8; ks++) {
            unsigned a[4];
            {
                int row = rA;
                unsigned addr = sb + (unsigned)(pwo + row * 256 + (ks >> 2) * 128)
                              + (((unsigned)((ks & 3) * 32) + hiA) ^ ((unsigned)(row & 7) * 16));
                ldsm_x4(a, addr);
            }
            unsigned b[4][4];
#pragma unroll
            for (int nj = 0; nj < 4; nj++) {
                int row = nj * 16 + rB;
                unsigned addr = sb + (unsigned)(FA_V + row * 272 + ks * 32) + hiB;
                ldsm_x4(b[nj], addr);
            }
#pragma unroll
            for (int nf = 0; nf < 8; nf++)
                mma_tf32(o[nf], a, b[nf >> 1][(nf & 1) * 2], b[nf >> 1][(nf & 1) * 2 + 1]);
        }
    }

    // ---- epilogue: normalize, tf32-round, store
    const float i0 = 1.f / l0, i1 = 1.f / l1;
    const int r0 = qbase + wid * 16 + g;
#pragma unroll
    for (int nf = 0; nf < 8; nf++) {
        int col = h * HD + nf * 8 + qq * 2;
        float2 v0 = make_float2(round_tf32(o[nf][0] * i0), round_tf32(o[nf][1] * i0));
        float2 v1 = make_float2(round_tf32(o[nf][2] * i1), round_tf32(o[nf][3] * i1));
        *(float2*)(attn + (size_t)r0 * D_EMBED + col)       = v0;
        *(float2*)(attn + (size_t)(r0 + 8) * D_EMBED + col) = v1;
    }
}

// ===========================================================================
extern "C" void kernel_launch(void* const* d_in, const int* in_sizes, int n_in,
                              void* d_out, int out_size)
{
    const float* hidden = (const float*)d_in[0];
    const float* w_qkv  = (const float*)d_in[1];
    const float* b_qkv  = (const float*)d_in[2];
    const float* w_out  = (const float*)d_in[3];
    const float* b_out  = (const float*)d_in[4];
    float* out = (float*)d_out;

    float *qkv, *attn, *hid_t, *wqkv_t, *wout_t;
    cudaGetSymbolAddress((void**)&qkv,    g_qkv);
    cudaGetSymbolAddress((void**)&attn,   g_attn);
    cudaGetSymbolAddress((void**)&hid_t,  g_hid_t);
    cudaGetSymbolAddress((void**)&wqkv_t, g_wqkv_t);
    cudaGetSymbolAddress((void**)&wout_t, g_wout_t);

    cudaFuncSetAttribute(gemm_tf32mma, cudaFuncAttributeMaxDynamicSharedMemorySize,
                         GEMM_SMEM_BYTES);
    cudaFuncSetAttribute(flash_attn_mma, cudaFuncAttributeMaxDynamicSharedMemorySize,
                         FA_SMEM);

    // RN-round all GEMM inputs to tf32 (single launch)
    round_all_kernel<<<(N4_ALL + 255) / 256, 256>>>(
        (const float4*)hidden, (const float4*)w_qkv, (const float4*)w_out,
        (float4*)hid_t, (float4*)wqkv_t, (float4*)wout_t);

    // 1) QKV projection (persistent tf32 mma.sync), output tf32-rounded
    gemm_tf32mma<<<GEMM_GRID, 256, GEMM_SMEM_BYTES>>>(
        hid_t, wqkv_t, b_qkv, qkv, D3, D_EMBED, SEQ, 1);

    // 2) Causal multi-head attention (tf32 mma.sync flash, LPT order)
    flash_attn_mma<<<dim3(SEQ / 64, NH), 128, FA_SMEM>>>(qkv, attn);

    // 3) Output projection (persistent tf32 mma.sync), full fp32 output
    gemm_tf32mma<<<GEMM_GRID, 256, GEMM_SMEM_BYTES>>>(
        attn, wout_t, b_out, out, D_EMBED, D_EMBED, SEQ, 0);
}

// round 14
// speedup vs baseline: 1.0508x; 1.0508x over previous
#include <cuda_runtime.h>
#include <math.h>

#define D_EMBED 2048
#define SEQ     2048
#define NH      32
#define HD      64
#define D3      (3 * D_EMBED)       // 6144

// Scratch (allocation-free rule)
__device__ float g_qkv[SEQ * D3];             // [2048,6144] qkv (tf32-rounded)
__device__ float g_attn[SEQ * D_EMBED];       // [2048,2048] attn out (tf32-rounded)
__device__ float g_hid_t[SEQ * D_EMBED];      // tf32-rounded hidden
__device__ float g_wqkv_t[D3 * D_EMBED];      // tf32-rounded w_qkv
__device__ float g_wout_t[D_EMBED * D_EMBED]; // tf32-rounded w_out

// ===========================================================================
// Helpers (base sm_100 portable: mma.sync / ldmatrix / cp.async only)
// ===========================================================================
__device__ __forceinline__ unsigned smem_u32(const void* p) {
    unsigned a;
    asm("{ .reg .u64 t; cvta.to.shared.u64 t, %1; cvt.u32.u64 %0, t; }"
        : "=r"(a) : "l"(p));
    return a;
}
#define CP_ASYNC16(dst, src) \
    asm volatile("cp.async.cg.shared.global [%0], [%1], 16;" :: "r"(dst), "l"(src))
#define CP_COMMIT() asm volatile("cp.async.commit_group;" ::: "memory")
#define CP_WAIT(n)  asm volatile("cp.async.wait_group %0;" :: "n"(n) : "memory")

__device__ __forceinline__ void ldsm_x4(unsigned r[4], unsigned addr) {
    asm volatile("ldmatrix.sync.aligned.m8n8.x4.shared.b16 {%0,%1,%2,%3}, [%4];"
                 : "=r"(r[0]), "=r"(r[1]), "=r"(r[2]), "=r"(r[3]) : "r"(addr));
}
__device__ __forceinline__ void mma_tf32(float c[4], const unsigned a[4],
                                         unsigned b0, unsigned b1) {
    asm volatile("mma.sync.aligned.m16n8k8.row.col.f32.tf32.tf32.f32 "
                 "{%0,%1,%2,%3}, {%4,%5,%6,%7}, {%8,%9}, {%0,%1,%2,%3};"
                 : "+f"(c[0]), "+f"(c[1]), "+f"(c[2]), "+f"(c[3])
                 : "r"(a[0]), "r"(a[1]), "r"(a[2]), "r"(a[3]), "r"(b0), "r"(b1));
}
__device__ __forceinline__ float round_tf32(float x) {
    unsigned u;
    asm("cvt.rna.tf32.f32 %0, %1;" : "=r"(u) : "f"(x));
    return __uint_as_float(u);
}
__device__ __forceinline__ float fast_exp2(float x) {
    float y;
    asm("ex2.approx.f32 %0, %1;" : "=f"(y) : "f"(x));
    return y;
}

// ===========================================================================
// Fused RN-round-to-tf32 over the three GEMM-input buffers (1 launch)
// ===========================================================================
#define N4_HID  (SEQ * D_EMBED / 4)
#define N4_WQKV (D3 * D_EMBED / 4)
#define N4_WOUT (D_EMBED * D_EMBED / 4)
#define N4_ALL  (N4_HID + N4_WQKV + N4_WOUT)

__global__ void round_all_kernel(const float4* __restrict__ hid,
                                 const float4* __restrict__ wqkv,
                                 const float4* __restrict__ wout,
                                 float4* __restrict__ hid_t,
                                 float4* __restrict__ wqkv_t,
                                 float4* __restrict__ wout_t)
{
    int i = blockIdx.x * blockDim.x + threadIdx.x;
    if (i >= N4_ALL) return;
    const float4* src;
    float4* dst;
    int j;
    if (i < N4_HID)                { src = hid;  dst = hid_t;  j = i; }
    else if (i < N4_HID + N4_WQKV) { src = wqkv; dst = wqkv_t; j = i - N4_HID; }
    else                           { src = wout; dst = wout_t; j = i - N4_HID - N4_WQKV; }
    float4 v = src[j];
    v.x = round_tf32(v.x); v.y = round_tf32(v.y);
    v.z = round_tf32(v.z); v.w = round_tf32(v.w);
    dst[j] = v;
}

// ===========================================================================
// tf32 mma.sync NT GEMM + bias, PERSISTENT grid (R8-proven, untouched).
// ===========================================================================
#define BM 128
#define BN 128
#define BK 32
#define STAGES 3
#define AS_BYTES (BM * 128)
#define BS_BYTES (BN * 128)
#define STG_BYTES (AS_BYTES + BS_BYTES)
#define GEMM_SMEM_BYTES (STAGES * STG_BYTES)  // 96 KB
#define GEMM_GRID 296                          // 148 SMs x 2 resident CTAs

__global__ __launch_bounds__(256, 2)
void gemm_tf32mma(const float* __restrict__ A, const float* __restrict__ B,
                  const float* __restrict__ bias, float* __restrict__ C,
                  int N, int K, int M, int round_c)
{
    extern __shared__ char smem[];
    const unsigned sb = smem_u32(smem);
    const int tid  = threadIdx.x;
    const int wid  = tid >> 5;
    const int lane = tid & 31;
    const int m_off = (wid & 1) * 64;
    const int n_off = (wid >> 1) * 32;
    const int NC = K / BK;
    const int ntx = N / BN;
    const int ntiles = ntx * (M / BM);

    const int rA  = lane & 15;
    const unsigned hiA = ((lane >> 4) & 1) * 16;
    const int rB  = (lane & 7) + ((lane >> 4) & 1) * 8;
    const unsigned hiB = ((lane >> 3) & 1) * 16;
    const int g = lane >> 2;
    const int cc = (lane & 3) * 2;

    for (int t = blockIdx.x; t < ntiles; t += gridDim.x) {
        const int m0 = (t / ntx) * BM;
        const int n0 = (t % ntx) * BN;

        __syncthreads();            // all warps done reading smem of prev tile

        float acc[4][4][4];
#pragma unroll
        for (int mi = 0; mi < 4; mi++)
#pragma unroll
            for (int nf = 0; nf < 4; nf++)
#pragma unroll
                for (int j = 0; j < 4; j++) acc[mi][nf][j] = 0.f;

        auto load_chunk = [&](int ck, int st) {
            const unsigned ab = sb + st * STG_BYTES;
            const unsigned bb = ab + AS_BYTES;
            const float* Ag = A + (size_t)m0 * K + ck * BK;
            const float* Bg = B + (size_t)n0 * K + ck * BK;
#pragma unroll
            for (int i = 0; i < 4; i++) {
                int seg = tid + i * 256;
                int r = seg >> 3, s16 = seg & 7;
                unsigned col = (unsigned)(s16 * 16) ^ ((unsigned)(r & 7) * 16);
                CP_ASYNC16(ab + r * 128 + col, Ag + (size_t)r * K + s16 * 4);
                CP_ASYNC16(bb + r * 128 + col, Bg + (size_t)r * K + s16 * 4);
            }
            CP_COMMIT();
        };

        for (int p = 0; p < STAGES - 1; p++) load_chunk(p, p);

        for (int c = 0; c < NC; c++) {
            CP_WAIT(STAGES - 2);
            __syncthreads();
            if (c + STAGES - 1 < NC) load_chunk(c + STAGES - 1, (c + STAGES - 1) % STAGES);
            else                     CP_COMMIT();

            const unsigned ab = sb + (c % STAGES) * STG_BYTES;
            const unsigned bb = ab + AS_BYTES;
#pragma unroll
            for (int ks = 0; ks < 4; ks++) {
                unsigned a[4][4], b[2][4];
#pragma unroll
                for (int mi = 0; mi < 4; mi++) {
                    int row = m_off + mi * 16 + rA;
                    unsigned col = ((unsigned)(ks * 32) + hiA) ^ ((unsigned)(row & 7) * 16);
                    ldsm_x4(a[mi], ab + row * 128 + col);
                }
#pragma unroll
                for (int nj = 0; nj < 2; nj++) {
                    int row = n_off + nj * 16 + rB;
                    unsigned col = ((unsigned)(ks * 32) + hiB) ^ ((unsigned)(row & 7) * 16);
                    ldsm_x4(b[nj], bb + row * 128 + col);
                }
#pragma unroll
                for (int mi = 0; mi < 4; mi++)
#pragma unroll
                    for (int nf = 0; nf < 4; nf++)
                        mma_tf32(acc[mi][nf], a[mi],
                                 b[nf >> 1][(nf & 1) * 2], b[nf >> 1][(nf & 1) * 2 + 1]);
            }
        }

#pragma unroll
        for (int nf = 0; nf < 4; nf++) {
            int col = n0 + n_off + nf * 8 + cc;
            float b0 = bias[col], b1 = bias[col + 1];
#pragma unroll
            for (int mi = 0; mi < 4; mi++) {
                int r = m0 + m_off + mi * 16 + g;
                float2 v0 = make_float2(acc[mi][nf][0] + b0, acc[mi][nf][1] + b1);
                float2 v1 = make_float2(acc[mi][nf][2] + b0, acc[mi][nf][3] + b1);
                if (round_c) {
                    v0.x = round_tf32(v0.x); v0.y = round_tf32(v0.y);
                    v1.x = round_tf32(v1.x); v1.y = round_tf32(v1.y);
                }
                *(float2*)(C + (size_t)r * N + col)       = v0;
                *(float2*)(C + (size_t)(r + 8) * N + col) = v1;
            }
        }
    }
}

// ===========================================================================
// tf32 mma.sync causal flash attention — EXACT R8 version (675.9us proven):
//  - LPT: qb = gridDim.x-1-blockIdx.x (longest CTAs first)
//  - V gather LDGs into registers before S MMA; STS after
//  - next-K prefetch after S MMA; Q re-ldmatrix'd per iteration (no reg cache)
// ===========================================================================
#define FA_Q 0
#define FA_K 16384                  // 2 stages x 16 KB
#define FA_V 49152                  // 64 x 272 B = 17408
#define FA_P 66560                  // 4 warps x 4 KB
#define FA_SMEM 82944
#define CST 0.1803368801111137f     // (1/8) * log2(e)

__global__ __launch_bounds__(128)
void flash_attn_mma(const float* __restrict__ qkv, float* __restrict__ attn)
{
    extern __shared__ char smc[];
    const unsigned sb = smem_u32(smc);
    const int tid = threadIdx.x;
    const int wid = tid >> 5, lane = tid & 31;
    const int qb = gridDim.x - 1 - blockIdx.x;     // LPT: big CTAs first
    const int h  = blockIdx.y;
    const int qbase = qb * 64;
    const int g = lane >> 2, qq = lane & 3;

    const int rA = lane & 15;
    const unsigned hiA = ((lane >> 4) & 1) * 16;
    const int rB = (lane & 7) + ((lane >> 4) & 1) * 8;
    const unsigned hiB = ((lane >> 3) & 1) * 16;

    // 64x64 f32 tile copy: 256B rows, XOR-16B swizzle per 128B half
    auto tile_async = [&](const float* gsrc, unsigned dstb) {
#pragma unroll
        for (int i = 0; i < 8; i++) {
            int u = tid + i * 128;
            int r = u >> 4, hs = (u >> 3) & 1, s16 = u & 7;
            unsigned off = ((unsigned)(s16 * 16)) ^ ((unsigned)(r & 7) * 16);
            CP_ASYNC16(dstb + (unsigned)(r * 256 + hs * 128) + off,
                       gsrc + (size_t)r * D3 + hs * 32 + s16 * 4);
        }
    };

    const float* Qg = qkv + (size_t)qbase * D3 + h * HD;
    const float* Kg = qkv + D_EMBED + h * HD;
    const float* Vg = qkv + 2 * D_EMBED + h * HD;

    tile_async(Qg, sb + FA_Q);
    tile_async(Kg, sb + FA_K);      // K tile 0 -> stage 0
    CP_COMMIT();

    float o[8][4];
#pragma unroll
    for (int nf = 0; nf < 8; nf++)
#pragma unroll
        for (int j = 0; j < 4; j++) o[nf][j] = 0.f;
    float m0 = -1e30f, m1 = -1e30f, l0 = 0.f, l1 = 0.f;

    const int vd = tid & 63, vkh = tid >> 6;       // V gather mapping

    for (int kt = 0; kt <= qb; kt++) {
        const int st = kt & 1;
        CP_WAIT(0);                 // K[kt] (and Q on first iter) resident
        __syncthreads();            // all warps done with prev tile (VsT reuse safe)

        // ---- V gather LDGs -> registers (overlap with S MMA below)
        float4 vr[8];
        {
            const float* src = Vg + (size_t)kt * 64 * D3 + vd;
#pragma unroll
            for (int j = 0; j < 8; j++) {
                int k0 = vkh * 32 + j * 4;
                vr[j].x = src[(size_t)(k0 + 0) * D3];
                vr[j].y = src[(size_t)(k0 + 1) * D3];
                vr[j].z = src[(size_t)(k0 + 2) * D3];
                vr[j].w = src[(size_t)(k0 + 3) * D3];
            }
        }

        // ---- S = Q K^T  (16 q-rows x 64 keys per warp)
        const unsigned kb = sb + FA_K + st * 16384;
        float sf[8][4];
#pragma unroll
        for (int nf = 0; nf < 8; nf++)
#pragma unroll
            for (int j = 0; j < 4; j++) sf[nf][j] = 0.f;
#pragma unroll
        for (int ks = 0; ks < 8; ks++) {
            unsigned a[4];
            {
                int row = wid * 16 + rA;
                unsigned addr = sb + FA_Q + (unsigned)(row * 256 + (ks >> 2) * 128)
                              + (((unsigned)((ks & 3) * 32) + hiA) ^ ((unsigned)(row & 7) * 16));
                ldsm_x4(a, addr);
            }
            unsigned b[4][4];
#pragma unroll
            for (int nj = 0; nj < 4; nj++) {
                int row = nj * 16 + rB;
                unsigned addr = kb + (unsigned)(row * 256 + (ks >> 2) * 128)
                              + (((unsigned)((ks & 3) * 32) + hiB) ^ ((unsigned)(row & 7) * 16));
                ldsm_x4(b[nj], addr);
            }
#pragma unroll
            for (int nf = 0; nf < 8; nf++)
                mma_tf32(sf[nf], a, b[nf >> 1][(nf & 1) * 2], b[nf >> 1][(nf & 1) * 2 + 1]);
        }

        // ---- prefetch next K tile into the other stage
        if (kt < qb)
            tile_async(Kg + (size_t)(kt + 1) * 64 * D3, sb + FA_K + (st ^ 1) * 16384);
        CP_COMMIT();

        // ---- V STS (loads landed during S MMA): VsT[d][key], row stride 272B
#pragma unroll
        for (int j = 0; j < 8; j++) {
            int k0 = vkh * 32 + j * 4;
            *(float4*)(smc + FA_V + vd * 272 + k0 * 4) = vr[j];
        }

        // ---- online softmax on fragments (log2 domain)
        if (kt == qb) {
            int r0 = qbase + wid * 16 + g;
#pragma unroll
            for (int nf = 0; nf < 8; nf++) {
                int col = qbase + nf * 8 + qq * 2;
                if (col > r0)         sf[nf][0] = -1e30f;
                if (col + 1 > r0)     sf[nf][1] = -1e30f;
                if (col > r0 + 8)     sf[nf][2] = -1e30f;
                if (col + 1 > r0 + 8) sf[nf][3] = -1e30f;
            }
        }
        float t0 = -1e30f, t1 = -1e30f;
#pragma unroll
        for (int nf = 0; nf < 8; nf++) {
            t0 = fmaxf(t0, fmaxf(sf[nf][0], sf[nf][1]));
            t1 = fmaxf(t1, fmaxf(sf[nf][2], sf[nf][3]));
        }
        t0 = fmaxf(t0, __shfl_xor_sync(0xffffffffu, t0, 1));
        t0 = fmaxf(t0, __shfl_xor_sync(0xffffffffu, t0, 2));
        t1 = fmaxf(t1, __shfl_xor_sync(0xffffffffu, t1, 1));
        t1 = fmaxf(t1, __shfl_xor_sync(0xffffffffu, t1, 2));
        const float mn0 = fmaxf(m0, t0 * CST);
        const float mn1 = fmaxf(m1, t1 * CST);
        const float al0 = fast_exp2(m0 - mn0);
        const float al1 = fast_exp2(m1 - mn1);
        m0 = mn0; m1 = mn1;

        float ps0 = 0.f, ps1 = 0.f;
        const int pwo = FA_P + wid * 4096;
#pragma unroll
        for (int nf = 0; nf < 8; nf++) {
            float p00 = round_tf32(fast_exp2(fmaf(sf[nf][0], CST, -mn0)));
            float p01 = round_tf32(fast_exp2(fmaf(sf[nf][1], CST, -mn0)));
            float p10 = round_tf32(fast_exp2(fmaf(sf[nf][2], CST, -mn1)));
            float p11 = round_tf32(fast_exp2(fmaf(sf[nf][3], CST, -mn1)));
            ps0 += p00 + p01; ps1 += p10 + p11;
            unsigned offh = ((unsigned)((nf & 3) * 32 + qq * 8)) ^ ((unsigned)g * 16);
            int base = pwo + (nf >> 2) * 128 + (int)offh;
            *(float2*)(smc + base + g * 256)       = make_float2(p00, p01);
            *(float2*)(smc + base + (g + 8) * 256) = make_float2(p10, p11);
        }
        ps0 += __shfl_xor_sync(0xffffffffu, ps0, 1);
        ps0 += __shfl_xor_sync(0xffffffffu, ps0, 2);
        ps1 += __shfl_xor_sync(0xffffffffu, ps1, 1);
        ps1 += __shfl_xor_sync(0xffffffffu, ps1, 2);
        l0 = l0 * al0 + ps0;
        l1 = l1 * al1 + ps1;
#pragma unroll
        for (int nf = 0; nf < 8; nf++) {
            o[nf][0] *= al0; o[nf][1] *= al0;
            o[nf][2] *= al1; o[nf][3] *= al1;
        }
        __syncwarp();               // P visible within warp
        __syncthreads();            // VsT + P visible to all warps

        // ---- O += P * V  (P A-frags from smem, V^T B-frags)
#pragma unroll
        for (int ks = 0; ks < 8; ks++) {
            unsigned a[4];
            {
                int row = rA;
                unsigned addr = sb + (unsigned)(pwo + row * 256 + (ks >> 2) * 128)
                              + (((unsigned)((ks & 3) * 32) + hiA) ^ ((unsigned)(row & 7) * 16));
                ldsm_x4(a, addr);
            }
            unsigned b[4][4];
#pragma unroll
            for (int nj = 0; nj < 4; nj++) {
                int row = nj * 16 + rB;
                unsigned addr = sb + (unsigned)(FA_V + row * 272 + ks * 32) + hiB;
                ldsm_x4(b[nj], addr);
            }
#pragma unroll
            for (int nf = 0; nf < 8; nf++)
                mma_tf32(o[nf], a, b[nf >> 1][(nf & 1) * 2], b[nf >> 1][(nf & 1) * 2 + 1]);
        }
    }

    // ---- epilogue: normalize, tf32-round, store
    const float i0 = 1.f / l0, i1 = 1.f / l1;
    const int r0 = qbase + wid * 16 + g;
#pragma unroll
    for (int nf = 0; nf < 8; nf++) {
        int col = h * HD + nf * 8 + qq * 2;
        float2 v0 = make_float2(round_tf32(o[nf][0] * i0), round_tf32(o[nf][1] * i0));
        float2 v1 = make_float2(round_tf32(o[nf][2] * i1), round_tf32(o[nf][3] * i1));
        *(float2*)(attn + (size_t)r0 * D_EMBED + col)       = v0;
        *(float2*)(attn + (size_t)(r0 + 8) * D_EMBED + col) = v1;
    }
}

// ===========================================================================
extern "C" void kernel_launch(void* const* d_in, const int* in_sizes, int n_in,
                              void* d_out, int out_size)
{
    const float* hidden = (const float*)d_in[0];
    const float* w_qkv  = (const float*)d_in[1];
    const float* b_qkv  = (const float*)d_in[2];
    const float* w_out  = (const float*)d_in[3];
    const float* b_out  = (const float*)d_in[4];
    float* out = (float*)d_out;

    float *qkv, *attn, *hid_t, *wqkv_t, *wout_t;
    cudaGetSymbolAddress((void**)&qkv,    g_qkv);
    cudaGetSymbolAddress((void**)&attn,   g_attn);
    cudaGetSymbolAddress((void**)&hid_t,  g_hid_t);
    cudaGetSymbolAddress((void**)&wqkv_t, g_wqkv_t);
    cudaGetSymbolAddress((void**)&wout_t, g_wout_t);

    cudaFuncSetAttribute(gemm_tf32mma, cudaFuncAttributeMaxDynamicSharedMemorySize,
                         GEMM_SMEM_BYTES);
    cudaFuncSetAttribute(flash_attn_mma, cudaFuncAttributeMaxDynamicSharedMemorySize,
                         FA_SMEM);

    // RN-round all GEMM inputs to tf32 (single launch)
    round_all_kernel<<<(N4_ALL + 255) / 256, 256>>>(
        (const float4*)hidden, (const float4*)w_qkv, (const float4*)w_out,
        (float4*)hid_t, (float4*)wqkv_t, (float4*)wout_t);

    // 1) QKV projection (persistent tf32 mma.sync), output tf32-rounded
    gemm_tf32mma<<<GEMM_GRID, 256, GEMM_SMEM_BYTES>>>(
        hid_t, wqkv_t, b_qkv, qkv, D3, D_EMBED, SEQ, 1);

    // 2) Causal multi-head attention (tf32 mma.sync flash, LPT order)
    flash_attn_mma<<<dim3(SEQ / 64, NH), 128, FA_SMEM>>>(qkv, attn);

    // 3) Output projection (persistent tf32 mma.sync), full fp32 output
    gemm_tf32mma<<<GEMM_GRID, 256, GEMM_SMEM_BYTES>>>(
        attn, wout_t, b_out, out, D_EMBED, D_EMBED, SEQ, 0);
}

// round 15
// speedup vs baseline: 1.0763x; 1.0243x over previous
#include <cuda_runtime.h>
#include <math.h>

#define D_EMBED 2048
#define SEQ     2048
#define NH      32
#define HD      64
#define D3      (3 * D_EMBED)       // 6144

// Scratch (allocation-free rule)
__device__ float g_qkv[SEQ * D3];             // [2048,6144] qkv (tf32-rounded)
__device__ float g_attn[SEQ * D_EMBED];       // [2048,2048] attn out (tf32-rounded)
__device__ float g_hid_t[SEQ * D_EMBED];      // tf32-rounded hidden
__device__ float g_wqkv_t[D3 * D_EMBED];      // tf32-rounded w_qkv
__device__ float g_wout_t[D_EMBED * D_EMBED]; // tf32-rounded w_out

// ===========================================================================
// Helpers (base sm_100 portable: mma.sync / ldmatrix / cp.async only)
// ===========================================================================
__device__ __forceinline__ unsigned smem_u32(const void* p) {
    unsigned a;
    asm("{ .reg .u64 t; cvta.to.shared.u64 t, %1; cvt.u32.u64 %0, t; }"
        : "=r"(a) : "l"(p));
    return a;
}
#define CP_ASYNC16(dst, src) \
    asm volatile("cp.async.cg.shared.global [%0], [%1], 16;" :: "r"(dst), "l"(src))
#define CP_COMMIT() asm volatile("cp.async.commit_group;" ::: "memory")
#define CP_WAIT(n)  asm volatile("cp.async.wait_group %0;" :: "n"(n) : "memory")

__device__ __forceinline__ void ldsm_x4(unsigned r[4], unsigned addr) {
    asm volatile("ldmatrix.sync.aligned.m8n8.x4.shared.b16 {%0,%1,%2,%3}, [%4];"
                 : "=r"(r[0]), "=r"(r[1]), "=r"(r[2]), "=r"(r[3]) : "r"(addr));
}
__device__ __forceinline__ void mma_tf32(float c[4], const unsigned a[4],
                                         unsigned b0, unsigned b1) {
    asm volatile("mma.sync.aligned.m16n8k8.row.col.f32.tf32.tf32.f32 "
                 "{%0,%1,%2,%3}, {%4,%5,%6,%7}, {%8,%9}, {%0,%1,%2,%3};"
                 : "+f"(c[0]), "+f"(c[1]), "+f"(c[2]), "+f"(c[3])
                 : "r"(a[0]), "r"(a[1]), "r"(a[2]), "r"(a[3]), "r"(b0), "r"(b1));
}
__device__ __forceinline__ float round_tf32(float x) {
    unsigned u;
    asm("cvt.rna.tf32.f32 %0, %1;" : "=r"(u) : "f"(x));
    return __uint_as_float(u);
}
__device__ __forceinline__ float fast_exp2(float x) {
    float y;
    asm("ex2.approx.f32 %0, %1;" : "=f"(y) : "f"(x));
    return y;
}

// ===========================================================================
// Fused RN-round-to-tf32 over the three GEMM-input buffers (1 launch)
// ===========================================================================
#define N4_HID  (SEQ * D_EMBED / 4)
#define N4_WQKV (D3 * D_EMBED / 4)
#define N4_WOUT (D_EMBED * D_EMBED / 4)
#define N4_ALL  (N4_HID + N4_WQKV + N4_WOUT)

__global__ void round_all_kernel(const float4* __restrict__ hid,
                                 const float4* __restrict__ wqkv,
                                 const float4* __restrict__ wout,
                                 float4* __restrict__ hid_t,
                                 float4* __restrict__ wqkv_t,
                                 float4* __restrict__ wout_t)
{
    int i = blockIdx.x * blockDim.x + threadIdx.x;
    if (i >= N4_ALL) return;
    const float4* src;
    float4* dst;
    int j;
    if (i < N4_HID)                { src = hid;  dst = hid_t;  j = i; }
    else if (i < N4_HID + N4_WQKV) { src = wqkv; dst = wqkv_t; j = i - N4_HID; }
    else                           { src = wout; dst = wout_t; j = i - N4_HID - N4_WQKV; }
    float4 v = src[j];
    v.x = round_tf32(v.x); v.y = round_tf32(v.y);
    v.z = round_tf32(v.z); v.w = round_tf32(v.w);
    dst[j] = v;
}

// ===========================================================================
// tf32 mma.sync NT GEMM + bias, persistent grid.
// NEW: BM=128, BN=256, 8 warps (2m x 4n), warp tile 64x64 -> 32 MMA : 8 LDSM.
// 1 CTA/SM (128 acc regs/thread), 3-stage cp.async, 144 KB smem.
// ===========================================================================
#define BM 128
#define BN 256
#define BK 32
#define STAGES 3
#define AS_BYTES (BM * 128)                   // 16 KB
#define BS_BYTES (BN * 128)                   // 32 KB
#define STG_BYTES (AS_BYTES + BS_BYTES)       // 48 KB
#define GEMM_SMEM_BYTES (STAGES * STG_BYTES)  // 144 KB
#define GEMM_GRID 148                          // 1 CTA per SM

__global__ __launch_bounds__(256, 1)
void gemm_tf32mma(const float* __restrict__ A, const float* __restrict__ B,
                  const float* __restrict__ bias, float* __restrict__ C,
                  int N, int K, int M, int round_c)
{
    extern __shared__ char smem[];
    const unsigned sb = smem_u32(smem);
    const int tid  = threadIdx.x;
    const int wid  = tid >> 5;
    const int lane = tid & 31;
    const int m_off = (wid & 1) * 64;         // 2 m-warps
    const int n_off = (wid >> 1) * 64;        // 4 n-warps
    const int NC = K / BK;
    const int ntx = N / BN;
    const int ntiles = ntx * (M / BM);

    const int rA  = lane & 15;
    const unsigned hiA = ((lane >> 4) & 1) * 16;
    const int rB  = (lane & 7) + ((lane >> 4) & 1) * 8;
    const unsigned hiB = ((lane >> 3) & 1) * 16;
    const int g = lane >> 2;
    const int cc = (lane & 3) * 2;

    for (int t = blockIdx.x; t < ntiles; t += gridDim.x) {
        const int m0 = (t / ntx) * BM;
        const int n0 = (t % ntx) * BN;

        __syncthreads();            // all warps done reading smem of prev tile

        float acc[4][8][4];         // [m-frag][n-frag][c]
#pragma unroll
        for (int mi = 0; mi < 4; mi++)
#pragma unroll
            for (int nf = 0; nf < 8; nf++)
#pragma unroll
                for (int j = 0; j < 4; j++) acc[mi][nf][j] = 0.f;

        auto load_chunk = [&](int ck, int st) {
            const unsigned ab = sb + st * STG_BYTES;
            const unsigned bb = ab + AS_BYTES;
            const float* Ag = A + (size_t)m0 * K + ck * BK;
            const float* Bg = B + (size_t)n0 * K + ck * BK;
#pragma unroll
            for (int i = 0; i < 4; i++) {     // A: 1024 segs
                int seg = tid + i * 256;
                int r = seg >> 3, s16 = seg & 7;
                unsigned col = (unsigned)(s16 * 16) ^ ((unsigned)(r & 7) * 16);
                CP_ASYNC16(ab + r * 128 + col, Ag + (size_t)r * K + s16 * 4);
            }
#pragma unroll
            for (int i = 0; i < 8; i++) {     // B: 2048 segs
                int seg = tid + i * 256;
                int r = seg >> 3, s16 = seg & 7;
                unsigned col = (unsigned)(s16 * 16) ^ ((unsigned)(r & 7) * 16);
                CP_ASYNC16(bb + r * 128 + col, Bg + (size_t)r * K + s16 * 4);
            }
            CP_COMMIT();
        };

        for (int p = 0; p < STAGES - 1; p++) load_chunk(p, p);

        for (int c = 0; c < NC; c++) {
            CP_WAIT(STAGES - 2);
            __syncthreads();
            if (c + STAGES - 1 < NC) load_chunk(c + STAGES - 1, (c + STAGES - 1) % STAGES);
            else                     CP_COMMIT();

            const unsigned ab = sb + (c % STAGES) * STG_BYTES;
            const unsigned bb = ab + AS_BYTES;
#pragma unroll
            for (int ks = 0; ks < 4; ks++) {
                unsigned a[4][4], b[4][4];
#pragma unroll
                for (int mi = 0; mi < 4; mi++) {
                    int row = m_off + mi * 16 + rA;
                    unsigned col = ((unsigned)(ks * 32) + hiA) ^ ((unsigned)(row & 7) * 16);
                    ldsm_x4(a[mi], ab + row * 128 + col);
                }
#pragma unroll
                for (int nj = 0; nj < 4; nj++) {
                    int row = n_off + nj * 16 + rB;
                    unsigned col = ((unsigned)(ks * 32) + hiB) ^ ((unsigned)(row & 7) * 16);
                    ldsm_x4(b[nj], bb + row * 128 + col);
                }
#pragma unroll
                for (int mi = 0; mi < 4; mi++)
#pragma unroll
                    for (int nf = 0; nf < 8; nf++)
                        mma_tf32(acc[mi][nf], a[mi],
                                 b[nf >> 1][(nf & 1) * 2], b[nf >> 1][(nf & 1) * 2 + 1]);
            }
        }

#pragma unroll
        for (int nf = 0; nf < 8; nf++) {
            int col = n0 + n_off + nf * 8 + cc;
            float b0 = bias[col], b1 = bias[col + 1];
#pragma unroll
            for (int mi = 0; mi < 4; mi++) {
                int r = m0 + m_off + mi * 16 + g;
                float2 v0 = make_float2(acc[mi][nf][0] + b0, acc[mi][nf][1] + b1);
                float2 v1 = make_float2(acc[mi][nf][2] + b0, acc[mi][nf][3] + b1);
                if (round_c) {
                    v0.x = round_tf32(v0.x); v0.y = round_tf32(v0.y);
                    v1.x = round_tf32(v1.x); v1.y = round_tf32(v1.y);
                }
                *(float2*)(C + (size_t)r * N + col)       = v0;
                *(float2*)(C + (size_t)(r + 8) * N + col) = v1;
            }
        }
    }
}

// ===========================================================================
// tf32 mma.sync causal flash attention — EXACT 672.7us-proven version.
// ===========================================================================
#define FA_Q 0
#define FA_K 16384                  // 2 stages x 16 KB
#define FA_V 49152                  // 64 x 272 B = 17408
#define FA_P 66560                  // 4 warps x 4 KB
#define FA_SMEM 82944
#define CST 0.1803368801111137f     // (1/8) * log2(e)

__global__ __launch_bounds__(128)
void flash_attn_mma(const float* __restrict__ qkv, float* __restrict__ attn)
{
    extern __shared__ char smc[];
    const unsigned sb = smem_u32(smc);
    const int tid = threadIdx.x;
    const int wid = tid >> 5, lane = tid & 31;
    const int qb = gridDim.x - 1 - blockIdx.x;     // LPT: big CTAs first
    const int h  = blockIdx.y;
    const int qbase = qb * 64;
    const int g = lane >> 2, qq = lane & 3;

    const int rA = lane & 15;
    const unsigned hiA = ((lane >> 4) & 1) * 16;
    const int rB = (lane & 7) + ((lane >> 4) & 1) * 8;
    const unsigned hiB = ((lane >> 3) & 1) * 16;

    // 64x64 f32 tile copy: 256B rows, XOR-16B swizzle per 128B half
    auto tile_async = [&](const float* gsrc, unsigned dstb) {
#pragma unroll
        for (int i = 0; i < 8; i++) {
            int u = tid + i * 128;
            int r = u >> 4, hs = (u >> 3) & 1, s16 = u & 7;
            unsigned off = ((unsigned)(s16 * 16)) ^ ((unsigned)(r & 7) * 16);
            CP_ASYNC16(dstb + (unsigned)(r * 256 + hs * 128) + off,
                       gsrc + (size_t)r * D3 + hs * 32 + s16 * 4);
        }
    };

    const float* Qg = qkv + (size_t)qbase * D3 + h * HD;
    const float* Kg = qkv + D_EMBED + h * HD;
    const float* Vg = qkv + 2 * D_EMBED + h * HD;

    tile_async(Qg, sb + FA_Q);
    tile_async(Kg, sb + FA_K);      // K tile 0 -> stage 0
    CP_COMMIT();

    float o[8][4];
#pragma unroll
    for (int nf = 0; nf < 8; nf++)
#pragma unroll
        for (int j = 0; j < 4; j++) o[nf][j] = 0.f;
    float m0 = -1e30f, m1 = -1e30f, l0 = 0.f, l1 = 0.f;

    const int vd = tid & 63, vkh = tid >> 6;       // V gather mapping

    for (int kt = 0; kt <= qb; kt++) {
        const int st = kt & 1;
        CP_WAIT(0);                 // K[kt] (and Q on first iter) resident
        __syncthreads();            // all warps done with prev tile (VsT reuse safe)

        // ---- V gather LDGs -> registers (overlap with S MMA below)
        float4 vr[8];
        {
            const float* src = Vg + (size_t)kt * 64 * D3 + vd;
#pragma unroll
            for (int j = 0; j < 8; j++) {
                int k0 = vkh * 32 + j * 4;
                vr[j].x = src[(size_t)(k0 + 0) * D3];
                vr[j].y = src[(size_t)(k0 + 1) * D3];
                vr[j].z = src[(size_t)(k0 + 2) * D3];
                vr[j].w = src[(size_t)(k0 + 3) * D3];
            }
        }

        // ---- S = Q K^T  (16 q-rows x 64 keys per warp)
        const unsigned kb = sb + FA_K + st * 16384;
        float sf[8][4];
#pragma unroll
        for (int nf = 0; nf < 8; nf++)
#pragma unroll
            for (int j = 0; j < 4; j++) sf[nf][j] = 0.f;
#pragma unroll
        for (int ks = 0; ks < 8; ks++) {
            unsigned a[4];
            {
                int row = wid * 16 + rA;
                unsigned addr = sb + FA_Q + (unsigned)(row * 256 + (ks >> 2) * 128)
                              + (((unsigned)((ks & 3) * 32) + hiA) ^ ((unsigned)(row & 7) * 16));
                ldsm_x4(a, addr);
            }
            unsigned b[4][4];
#pragma unroll
            for (int nj = 0; nj < 4; nj++) {
                int row = nj * 16 + rB;
                unsigned addr = kb + (unsigned)(row * 256 + (ks >> 2) * 128)
                              + (((unsigned)((ks & 3) * 32) + hiB) ^ ((unsigned)(row & 7) * 16));
                ldsm_x4(b[nj], addr);
            }
#pragma unroll
            for (int nf = 0; nf < 8; nf++)
                mma_tf32(sf[nf], a, b[nf >> 1][(nf & 1) * 2], b[nf >> 1][(nf & 1) * 2 + 1]);
        }

        // ---- prefetch next K tile into the other stage
        if (kt < qb)
            tile_async(Kg + (size_t)(kt + 1) * 64 * D3, sb + FA_K + (st ^ 1) * 16384);
        CP_COMMIT();

        // ---- V STS (loads landed during S MMA): VsT[d][key], row stride 272B
#pragma unroll
        for (int j = 0; j < 8; j++) {
            int k0 = vkh * 32 + j * 4;
            *(float4*)(smc + FA_V + vd * 272 + k0 * 4) = vr[j];
        }

        // ---- online softmax on fragments (log2 domain)
        if (kt == qb) {
            int r0 = qbase + wid * 16 + g;
#pragma unroll
            for (int nf = 0; nf < 8; nf++) {
                int col = qbase + nf * 8 + qq * 2;
                if (col > r0)         sf[nf][0] = -1e30f;
                if (col + 1 > r0)     sf[nf][1] = -1e30f;
                if (col > r0 + 8)     sf[nf][2] = -1e30f;
                if (col + 1 > r0 + 8) sf[nf][3] = -1e30f;
            }
        }
        float t0 = -1e30f, t1 = -1e30f;
#pragma unroll
        for (int nf = 0; nf < 8; nf++) {
            t0 = fmaxf(t0, fmaxf(sf[nf][0], sf[nf][1]));
            t1 = fmaxf(t1, fmaxf(sf[nf][2], sf[nf][3]));
        }
        t0 = fmaxf(t0, __shfl_xor_sync(0xffffffffu, t0, 1));
        t0 = fmaxf(t0, __shfl_xor_sync(0xffffffffu, t0, 2));
        t1 = fmaxf(t1, __shfl_xor_sync(0xffffffffu, t1, 1));
        t1 = fmaxf(t1, __shfl_xor_sync(0xffffffffu, t1, 2));
        const float mn0 = fmaxf(m0, t0 * CST);
        const float mn1 = fmaxf(m1, t1 * CST);
        const float al0 = fast_exp2(m0 - mn0);
        const float al1 = fast_exp2(m1 - mn1);
        m0 = mn0; m1 = mn1;

        float ps0 = 0.f, ps1 = 0.f;
        const int pwo = FA_P + wid * 4096;
#pragma unroll
        for (int nf = 0; nf < 8; nf++) {
            float p00 = round_tf32(fast_exp2(fmaf(sf[nf][0], CST, -mn0)));
            float p01 = round_tf32(fast_exp2(fmaf(sf[nf][1], CST, -mn0)));
            float p10 = round_tf32(fast_exp2(fmaf(sf[nf][2], CST, -mn1)));
            float p11 = round_tf32(fast_exp2(fmaf(sf[nf][3], CST, -mn1)));
            ps0 += p00 + p01; ps1 += p10 + p11;
            unsigned offh = ((unsigned)((nf & 3) * 32 + qq * 8)) ^ ((unsigned)g * 16);
            int base = pwo + (nf >> 2) * 128 + (int)offh;
            *(float2*)(smc + base + g * 256)       = make_float2(p00, p01);
            *(float2*)(smc + base + (g + 8) * 256) = make_float2(p10, p11);
        }
        ps0 += __shfl_xor_sync(0xffffffffu, ps0, 1);
        ps0 += __shfl_xor_sync(0xffffffffu, ps0, 2);
        ps1 += __shfl_xor_sync(0xffffffffu, ps1, 1);
        ps1 += __shfl_xor_sync(0xffffffffu, ps1, 2);
        l0 = l0 * al0 + ps0;
        l1 = l1 * al1 + ps1;
#pragma unroll
        for (int nf = 0; nf < 8; nf++) {
            o[nf][0] *= al0; o[nf][1] *= al0;
            o[nf][2] *= al1; o[nf][3] *= al1;
        }
        __syncwarp();               // P visible within warp
        __syncthreads();            // VsT + P visible to all warps

        // ---- O += P * V  (P A-frags from smem, V^T B-frags)
#pragma unroll
        for (int ks = 0; ks < 8; ks++) {
            unsigned a[4];
            {
                int row = rA;
                unsigned addr = sb + (unsigned)(pwo + row * 256 + (ks >> 2) * 128)
                              + (((unsigned)((ks & 3) * 32) + hiA) ^ ((unsigned)(row & 7) * 16));
                ldsm_x4(a, addr);
            }
            unsigned b[4][4];
#pragma unroll
            for (int nj = 0; nj < 4; nj++) {
                int row = nj * 16 + rB;
                unsigned addr = sb + (unsigned)(FA_V + row * 272 + ks * 32) + hiB;
                ldsm_x4(b[nj], addr);
            }
#pragma unroll
            for (int nf = 0; nf < 8; nf++)
                mma_tf32(o[nf], a, b[nf >> 1][(nf & 1) * 2], b[nf >> 1][(nf & 1) * 2 + 1]);
        }
    }

    // ---- epilogue: normalize, tf32-round, store
    const float i0 = 1.f / l0, i1 = 1.f / l1;
    const int r0 = qbase + wid * 16 + g;
#pragma unroll
    for (int nf = 0; nf < 8; nf++) {
        int col = h * HD + nf * 8 + qq * 2;
        float2 v0 = make_float2(round_tf32(o[nf][0] * i0), round_tf32(o[nf][1] * i0));
        float2 v1 = make_float2(round_tf32(o[nf][2] * i1), round_tf32(o[nf][3] * i1));
        *(float2*)(attn + (size_t)r0 * D_EMBED + col)       = v0;
        *(float2*)(attn + (size_t)(r0 + 8) * D_EMBED + col) = v1;
    }
}

// ===========================================================================
extern "C" void kernel_launch(void* const* d_in, const int* in_sizes, int n_in,
                              void* d_out, int out_size)
{
    const float* hidden = (const float*)d_in[0];
    const float* w_qkv  = (const float*)d_in[1];
    const float* b_qkv  = (const float*)d_in[2];
    const float* w_out  = (const float*)d_in[3];
    const float* b_out  = (const float*)d_in[4];
    float* out = (float*)d_out;

    float *qkv, *attn, *hid_t, *wqkv_t, *wout_t;
    cudaGetSymbolAddress((void**)&qkv,    g_qkv);
    cudaGetSymbolAddress((void**)&attn,   g_attn);
    cudaGetSymbolAddress((void**)&hid_t,  g_hid_t);
    cudaGetSymbolAddress((void**)&wqkv_t, g_wqkv_t);
    cudaGetSymbolAddress((void**)&wout_t, g_wout_t);

    cudaFuncSetAttribute(gemm_tf32mma, cudaFuncAttributeMaxDynamicSharedMemorySize,
                         GEMM_SMEM_BYTES);
    cudaFuncSetAttribute(flash_attn_mma, cudaFuncAttributeMaxDynamicSharedMemorySize,
                         FA_SMEM);

    // RN-round all GEMM inputs to tf32 (single launch)
    round_all_kernel<<<(N4_ALL + 255) / 256, 256>>>(
        (const float4*)hidden, (const float4*)w_qkv, (const float4*)w_out,
        (float4*)hid_t, (float4*)wqkv_t, (float4*)wout_t);

    // 1) QKV projection (persistent tf32 mma.sync), output tf32-rounded
    gemm_tf32mma<<<GEMM_GRID, 256, GEMM_SMEM_BYTES>>>(
        hid_t, wqkv_t, b_qkv, qkv, D3, D_EMBED, SEQ, 1);

    // 2) Causal multi-head attention (tf32 mma.sync flash, LPT order)
    flash_attn_mma<<<dim3(SEQ / 64, NH), 128, FA_SMEM>>>(qkv, attn);

    // 3) Output projection (persistent tf32 mma.sync), full fp32 output
    gemm_tf32mma<<<GEMM_GRID, 256, GEMM_SMEM_BYTES>>>(
        attn, wout_t, b_out, out, D_EMBED, D_EMBED, SEQ, 0);
}